// round 14
// baseline (speedup 1.0000x reference)
#include <cuda_runtime.h>

// StereoDenoiser: B=8, C=3, H=1024, W=1920, fp32.
//   disp  = clip(depth*128, 0, 128)            [B,H,W]
//   warped_r = bilinear_x(img_r, x = w - disp) (border clamp)
//   warped_l = bilinear_x(img_l, x = w + disp)
//   out_l = (img_l + warped_r)*0.5 ; out_r = (img_r + warped_l)*0.5
// Output buffer: [out_l | out_r], each B*C*H*W floats.
//
// Strategy: one block per ROW PAIR (rows h, h+1 are contiguous in memory):
// per channel the block reads/writes 15.36 KB contiguous bursts per tensor —
// double the burst length and half the concurrent stream count of the
// one-row-per-block version, for better DRAM row-buffer locality. All taps
// served from smem; index math rematerialized per channel from cached depth.

#define BATCH 8
#define CH 3
#define HH 1024
#define WW 1920
#define HPAIRS (HH / 2)
#define MAXD 128.0f

__global__ __launch_bounds__(480) void stereo_denoise_kernel(
    const float* __restrict__ img_l,
    const float* __restrict__ img_r,
    const float* __restrict__ depth,
    float* __restrict__ out)
{
    __shared__ float sl[2 * WW];   // rows h, h+1 of img_l : 15360 B
    __shared__ float sr[2 * WW];   // rows h, h+1 of img_r : 15360 B

    const int bp = blockIdx.x;           // b * HPAIRS + hp
    const int b  = bp / HPAIRS;
    const int h  = (bp - b * HPAIRS) * 2;
    const int u  = threadIdx.x;          // 0..479
    const int w0 = u * 4;

    // long-lived per-pixel state: raw depth for both rows (8 regs)
    const int drow = (b * HH + h) * WW;
    float4 dep0 = *reinterpret_cast<const float4*>(depth + drow + w0);
    float4 dep1 = *reinterpret_cast<const float4*>(depth + drow + WW + w0);
    float d[8] = {dep0.x, dep0.y, dep0.z, dep0.w,
                  dep1.x, dep1.y, dep1.z, dep1.w};

    const int HW = HH * WW;
    const int N  = BATCH * CH * HW;            // 47,185,920 (fits int32)
    const int plane0 = (b * CH) * HW + h * WW; // c=0, row h base

#pragma unroll
    for (int c = 0; c < CH; ++c) {
        const int base = plane0 + c * HW;

        if (c) __syncthreads();                // protect smem before overwrite

        // stage both rows of both images: 4 independent coalesced LDG.128
        float4 lv0 = *reinterpret_cast<const float4*>(img_l + base + w0);
        float4 lv1 = *reinterpret_cast<const float4*>(img_l + base + WW + w0);
        float4 rv0 = *reinterpret_cast<const float4*>(img_r + base + w0);
        float4 rv1 = *reinterpret_cast<const float4*>(img_r + base + WW + w0);
        *reinterpret_cast<float4*>(sl + w0)       = lv0;
        *reinterpret_cast<float4*>(sl + WW + w0)  = lv1;
        *reinterpret_cast<float4*>(sr + w0)       = rv0;
        *reinterpret_cast<float4*>(sr + WW + w0)  = rv1;
        __syncthreads();

        float lvv[8] = {lv0.x, lv0.y, lv0.z, lv0.w, lv1.x, lv1.y, lv1.z, lv1.w};
        float rvv[8] = {rv0.x, rv0.y, rv0.z, rv0.w, rv1.x, rv1.y, rv1.z, rv1.w};

        float ol[8], og[8];
#pragma unroll
        for (int r = 0; r < 2; ++r) {
            const float* slr = sl + r * WW;
            const float* srr = sr + r * WW;
#pragma unroll
            for (int p = 0; p < 4; ++p) {
                const int q = r * 4 + p;
                // recompute indices/fractions from d[q] (remat, no spill)
                float disp = fminf(fmaxf(d[q] * MAXD, 0.0f), MAXD);
                float xw = (float)(w0 + p);

                float xl = fminf(fmaxf(xw - disp, 0.0f), (float)(WW - 1));
                int a0 = (int)xl;              // xl >= 0 -> trunc == floor
                float fl = xl - (float)a0;
                int a1 = min(a0 + 1, WW - 1);

                float xr = fminf(fmaxf(xw + disp, 0.0f), (float)(WW - 1));
                int b0 = (int)xr;
                float fr = xr - (float)b0;
                int b1 = min(b0 + 1, WW - 1);

                float wr = srr[a0] * (1.0f - fl) + srr[a1] * fl;
                float wl = slr[b0] * (1.0f - fr) + slr[b1] * fr;
                ol[q] = (lvv[q] + wr) * 0.5f;
                og[q] = (rvv[q] + wl) * 0.5f;
            }
        }

        *reinterpret_cast<float4*>(out + base + w0) =
            make_float4(ol[0], ol[1], ol[2], ol[3]);
        *reinterpret_cast<float4*>(out + base + WW + w0) =
            make_float4(ol[4], ol[5], ol[6], ol[7]);
        *reinterpret_cast<float4*>(out + N + base + w0) =
            make_float4(og[0], og[1], og[2], og[3]);
        *reinterpret_cast<float4*>(out + N + base + WW + w0) =
            make_float4(og[4], og[5], og[6], og[7]);
    }
}

extern "C" void kernel_launch(void* const* d_in, const int* in_sizes, int n_in,
                              void* d_out, int out_size) {
    const float* img_l = (const float*)d_in[0];
    const float* img_r = (const float*)d_in[1];
    const float* depth = (const float*)d_in[2];
    float* out = (float*)d_out;

    const int blocks = BATCH * HPAIRS;       // one block per row pair
    stereo_denoise_kernel<<<blocks, 480>>>(img_l, img_r, depth, out);
}

// round 16
// speedup vs baseline: 1.2716x; 1.2716x over previous
#include <cuda_runtime.h>

// StereoDenoiser: B=8, C=3, H=1024, W=1920, fp32.
//   disp  = clip(depth*128, 0, 128)            [B,H,W]
//   warped_r = bilinear_x(img_r, x = w - disp) (border clamp)
//   warped_l = bilinear_x(img_l, x = w + disp)
//   out_l = (img_l + warped_r)*0.5 ; out_r = (img_r + warped_l)*0.5
// Output buffer: [out_l | out_r], each B*C*H*W floats.
//
// Strategy: one block per (b,h) image row; DOUBLE-BUFFERED per-channel smem
// staging (channel c computes from buf[c&1] while c+1 stages into the other
// buffer). Only one barrier per channel (after STS): STS_{c+2} targets the
// buffer read by comp_c but is ordered after B_{c+1}, which each thread
// reaches only after finishing comp_c -> WAR safe with 3 barriers total.
// Fast warps stage the next channel while slow warps compute, keeping DRAM
// loads in flight across channel boundaries.

#define BATCH 8
#define CH 3
#define HH 1024
#define WW 1920
#define MAXD 128.0f

__global__ __launch_bounds__(480) void stereo_denoise_kernel(
    const float* __restrict__ img_l,
    const float* __restrict__ img_r,
    const float* __restrict__ depth,
    float* __restrict__ out)
{
    __shared__ float sl[2][WW];   // 15360 B
    __shared__ float sr[2][WW];   // 15360 B  (total 30720 B -> 2 CTAs/SM)

    const int row = blockIdx.x;          // b*HH + h
    const int b   = row / HH;
    const int u   = threadIdx.x;         // 0..479
    const int w0  = u * 4;

    // long-lived per-pixel state: raw depth (4 regs); indices rematerialized
    float4 dep = *reinterpret_cast<const float4*>(depth + (size_t)row * WW + w0);
    float d[4] = {dep.x, dep.y, dep.z, dep.w};

    const int HW = HH * WW;
    const int N  = BATCH * CH * HW;          // 47,185,920 (fits int32)
    const int plane0 = b * (CH - 1) * HW + row * WW;   // == b*CH*HW + h*WW

    // ---- stage channel 0 into buffer 0 ----
    float4 lv = *reinterpret_cast<const float4*>(img_l + plane0 + w0);
    float4 rv = *reinterpret_cast<const float4*>(img_r + plane0 + w0);
    *reinterpret_cast<float4*>(&sl[0][w0]) = lv;
    *reinterpret_cast<float4*>(&sr[0][w0]) = rv;
    __syncthreads();                         // B0

#pragma unroll
    for (int c = 0; c < CH; ++c) {
        const int base = plane0 + c * HW;
        const float* slc = sl[c & 1];
        const float* src = sr[c & 1];

        float lvv[4] = {lv.x, lv.y, lv.z, lv.w};
        float rvv[4] = {rv.x, rv.y, rv.z, rv.w};

        // prefetch channel c+1 (independent of compute below; ptxas may hoist)
        if (c + 1 < CH) {
            lv = *reinterpret_cast<const float4*>(img_l + base + HW + w0);
            rv = *reinterpret_cast<const float4*>(img_r + base + HW + w0);
        }

        float ol[4], og[4];
#pragma unroll
        for (int p = 0; p < 4; ++p) {
            // recompute indices/fractions from d[p] (remat, no spill)
            float disp = fminf(fmaxf(d[p] * MAXD, 0.0f), MAXD);
            float xw = (float)(w0 + p);

            float xl = fminf(fmaxf(xw - disp, 0.0f), (float)(WW - 1));
            int a0 = (int)xl;                // xl >= 0 -> trunc == floor
            float fl = xl - (float)a0;
            int a1 = min(a0 + 1, WW - 1);

            float xr = fminf(fmaxf(xw + disp, 0.0f), (float)(WW - 1));
            int b0 = (int)xr;
            float fr = xr - (float)b0;
            int b1 = min(b0 + 1, WW - 1);

            float wr = src[a0] * (1.0f - fl) + src[a1] * fl;
            float wl = slc[b0] * (1.0f - fr) + slc[b1] * fr;
            ol[p] = (lvv[p] + wr) * 0.5f;
            og[p] = (rvv[p] + wl) * 0.5f;
        }

        *reinterpret_cast<float4*>(out + base + w0) =
            make_float4(ol[0], ol[1], ol[2], ol[3]);
        *reinterpret_cast<float4*>(out + N + base + w0) =
            make_float4(og[0], og[1], og[2], og[3]);

        if (c + 1 < CH) {
            const int nb = (c + 1) & 1;
            *reinterpret_cast<float4*>(&sl[nb][w0]) = lv;
            *reinterpret_cast<float4*>(&sr[nb][w0]) = rv;
            __syncthreads();                 // B_{c+1}
        }
    }
}

extern "C" void kernel_launch(void* const* d_in, const int* in_sizes, int n_in,
                              void* d_out, int out_size) {
    const float* img_l = (const float*)d_in[0];
    const float* img_r = (const float*)d_in[1];
    const float* depth = (const float*)d_in[2];
    float* out = (float*)d_out;

    const int blocks = BATCH * HH;           // one block per image row
    stereo_denoise_kernel<<<blocks, 480>>>(img_l, img_r, depth, out);
}